// round 16
// baseline (speedup 1.0000x reference)
#include <cuda_runtime.h>
#include <cuda_fp16.h>
#include <math.h>
#include <stdint.h>

#define B 64
#define T 1024
#define E 512
#define R 1024
#define A 128
#define F 32
#define KS 31
#define PADC 15

#define TM 128          // t-tile of energy GEMM
#define KC 32           // k-chunk
#define NCHUNK 17       // 16 key chunks + 1 feat/Wloc chunk
#define SAH 40          // A smem row stride (halves) -> conflict-free frags
#define SBH 40          // B smem col stride (halves)
#define SZAH (TM * SAH) // 5120 halves = 10240 B
#define SZBH (A * SBH)  // 5120 halves = 10240 B
#define SMEM_BYTES ((2 * SZAH + 2 * SZBH) * 2)   // 40960 B

// prep grid layout
#define NB_LOC  256     // 4 per batch (256 t each)
#define NB_QP   256     // 4 per batch (256 r each, 2 thread-groups of 128 r)
#define NB_WB   68
#define NB_MS   16
#define NB_PREP (NB_LOC + NB_QP + NB_WB + NB_MS)

// scratch (allocation-free rule: __device__ globals)
__device__ float  g_qpart[B * 4 * A];
__device__ __half g_feath[(size_t)B * T * F];        // [B][T][F] half
__device__ float  g_e[B * T];
__device__ float4 g_ctxpart4[B * 16 * E / 4];
__device__ __half g_wbh[(E + F) * A];                // per-chunk [col a][k] half
__device__ int    g_mflags[2];
__device__ int    g_cnt[B];

// ---------------------------------------------------------------------------
__device__ __forceinline__ void cp16(void* dst_smem, const void* src) {
    uint32_t d = (uint32_t)__cvta_generic_to_shared(dst_smem);
    asm volatile("cp.async.ca.shared.global [%0], [%1], 16;" :: "r"(d), "l"(src));
}
__device__ __forceinline__ void mma_f16(float& c0, float& c1, float& c2, float& c3,
                                        uint32_t a0, uint32_t a1, uint32_t a2, uint32_t a3,
                                        uint32_t b0, uint32_t b1) {
    asm volatile(
        "mma.sync.aligned.m16n8k16.row.col.f32.f16.f16.f32 "
        "{%0,%1,%2,%3}, {%4,%5,%6,%7}, {%8,%9}, {%0,%1,%2,%3};"
        : "+f"(c0), "+f"(c1), "+f"(c2), "+f"(c3)
        : "r"(a0), "r"(a1), "r"(a2), "r"(a3), "r"(b0), "r"(b1));
}
__device__ __forceinline__ void ldsm_x4(uint32_t& r0, uint32_t& r1,
                                        uint32_t& r2, uint32_t& r3,
                                        const __half* p) {
    uint32_t a = (uint32_t)__cvta_generic_to_shared(p);
    asm volatile("ldmatrix.sync.aligned.m8n8.x4.shared.b16 {%0,%1,%2,%3}, [%4];"
                 : "=r"(r0), "=r"(r1), "=r"(r2), "=r"(r3) : "r"(a));
}
__device__ __forceinline__ bool read_mask(const void* m, int idx, int mode) {
    if (mode == 1) return ((const int*)m)[idx] != 0;
    if (mode == 2) return ((const float*)m)[idx] != 0.f;
    return ((const unsigned char*)m)[idx] != 0;
}
__device__ __forceinline__ uint32_t pack_h2(float a, float b) {
    __half2 h = __floats2half2_rn(a, b);
    return *(uint32_t*)&h;
}

// ---------------------------------------------------------------------------
// PREP: fused loc-conv / qproj-partials / wbT(half) / mask-sniff
// ---------------------------------------------------------------------------
__global__ void __launch_bounds__(256)
prep_kernel(const float* __restrict__ query,
            const float* __restrict__ Wq,
            const float* __restrict__ cat,
            const float* __restrict__ conv_w,
            const float* __restrict__ gamma,
            const float* __restrict__ beta,
            const float* __restrict__ mean,
            const float* __restrict__ var,
            const float* __restrict__ Wk,
            const float* __restrict__ Wloc,
            const unsigned int* __restrict__ maskw) {
    int blk = blockIdx.x;
    int tid = threadIdx.x;

    if (blk < NB_LOC) {
        // ------- loc: conv1d -> relu -> BN -> g_feath (direct per-thread write) ------
        int b  = blk >> 2;
        int t0 = (blk & 3) * 256;

        __shared__ float xs[2][288];
        __shared__ float cwT[2 * KS * F];
        __shared__ float bnS[F], bnB[F];

        for (int idx = tid; idx < 2 * 286; idx += 256) {
            int ch = idx / 286, p = idx % 286;
            int tt = t0 - PADC + p;
            xs[ch][p] = (tt >= 0 && tt < T)
                      ? cat[(size_t)b * 2 * T + (size_t)ch * T + tt] : 0.f;
        }
        for (int idx = tid; idx < 2 * KS * F; idx += 256) {
            int f = idx & 31;
            int rest = idx >> 5;
            int ch = rest / KS, k = rest % KS;
            cwT[idx] = conv_w[(f * 2 + ch) * KS + k];
        }
        if (tid < F) {
            float s = rsqrtf(var[tid] + 1e-5f) * gamma[tid];
            bnS[tid] = s;
            bnB[tid] = beta[tid] - mean[tid] * s;
        }
        __syncthreads();

        float4 acc[8];
        #pragma unroll
        for (int u = 0; u < 8; u++) acc[u] = make_float4(0.f, 0.f, 0.f, 0.f);

        #pragma unroll
        for (int ch = 0; ch < 2; ch++) {
            #pragma unroll
            for (int k = 0; k < KS; k++) {
                float xv = xs[ch][tid + k];
                const float4* c4 = (const float4*)(cwT + (ch * KS + k) * F);
                #pragma unroll
                for (int u = 0; u < 8; u++) {
                    float4 c = c4[u];
                    acc[u].x += xv * c.x; acc[u].y += xv * c.y;
                    acc[u].z += xv * c.z; acc[u].w += xv * c.w;
                }
            }
        }

        uint32_t h[16];
        #pragma unroll
        for (int u = 0; u < 8; u++) {
            int f0 = u * 4;
            float o0 = fmaxf(acc[u].x, 0.f) * bnS[f0 + 0] + bnB[f0 + 0];
            float o1 = fmaxf(acc[u].y, 0.f) * bnS[f0 + 1] + bnB[f0 + 1];
            float o2 = fmaxf(acc[u].z, 0.f) * bnS[f0 + 2] + bnB[f0 + 2];
            float o3 = fmaxf(acc[u].w, 0.f) * bnS[f0 + 3] + bnB[f0 + 3];
            h[u * 2 + 0] = pack_h2(o0, o1);
            h[u * 2 + 1] = pack_h2(o2, o3);
        }
        uint4* dst = (uint4*)(g_feath + ((size_t)b * T + t0 + tid) * F);
        dst[0] = make_uint4(h[0],  h[1],  h[2],  h[3]);
        dst[1] = make_uint4(h[4],  h[5],  h[6],  h[7]);
        dst[2] = make_uint4(h[8],  h[9],  h[10], h[11]);
        dst[3] = make_uint4(h[12], h[13], h[14], h[15]);
    } else if (blk < NB_LOC + NB_QP) {
        // ------------ qproj partials: 4 blocks/b x 2 groups of 128 r ------------
        int idx = blk - NB_LOC;
        int b = idx >> 2, rr = idx & 3;
        int g = tid >> 7, a = tid & 127;
        __shared__ float sred[2][128];
        const float* qb = query + (size_t)b * R + rr * 256 + g * 128;
        const float* wp = Wq + (size_t)(rr * 256 + g * 128) * A + a;
        float acc = 0.f;
        #pragma unroll 16
        for (int r = 0; r < 128; r++)
            acc += qb[r] * wp[(size_t)r * A];
        sred[g][a] = acc;
        __syncthreads();
        if (g == 0)
            g_qpart[(b * 4 + rr) * A + a] = sred[0][a] + sred[1][a];
    } else if (blk < NB_LOC + NB_QP + NB_WB) {
        // ------ wbT: Wk ++ Wloc -> half, transposed per chunk [col a][k] ------
        int base = (blk - NB_LOC - NB_QP) * 1024;
        #pragma unroll
        for (int i = 0; i < 4; i++) {
            int idx = base + i * 256 + tid;
            int kg = idx >> 7, a = idx & 127;
            float x = (idx < E * A) ? Wk[idx] : Wloc[idx - E * A];
            int chunk = kg >> 5, kl = kg & 31;
            g_wbh[(size_t)chunk * (KC * A) + a * KC + kl] = __float2half_rn(x);
        }
    } else {
        // ---------------- mask sniff (16 blocks) + counter reset ----------------
        int ms = blk - NB_LOC - NB_QP - NB_WB;
        if (ms == 0 && tid < B) g_cnt[tid] = 0;
        __shared__ int s_not_int, s_not_flt;
        if (tid == 0) { s_not_int = 0; s_not_flt = 0; }
        __syncthreads();
        int not_int = 0, not_flt = 0;
        #pragma unroll
        for (int i = 0; i < 4; i++) {
            unsigned int x = maskw[ms * 1024 + i * 256 + tid];
            if (x > 1u) not_int = 1;
            if (x != 0u && x != 0x3F800000u) not_flt = 1;
        }
        if (not_int) atomicOr(&s_not_int, 1);
        if (not_flt) atomicOr(&s_not_flt, 1);
        __syncthreads();
        if (tid == 0) {
            if (s_not_int) atomicOr(&g_mflags[0], 1);
            if (s_not_flt) atomicOr(&g_mflags[1], 1);
        }
    }
}

// ---------------------------------------------------------------------------
// energy: fp16 MMA (m16n8k16), ldmatrix loads, A+B double-buffered,
// ONE barrier per chunk
// ---------------------------------------------------------------------------
__global__ void __launch_bounds__(256, 2)
energy_kernel(const float* __restrict__ key,
              const void* __restrict__ mask,
              const float* __restrict__ v) {
    int b  = blockIdx.y;
    int t0 = blockIdx.x * TM;
    int tid = threadIdx.x;
    int lane = tid & 31;
    int wid  = tid >> 5;
    int warp_m = wid >> 2;
    int warp_n = wid & 3;
    int lg = lane >> 3;
    int lr = lane & 7;

    extern __shared__ char dsmc[];
    __half* stA[2] = {(__half*)dsmc, (__half*)dsmc + SZAH};
    __half* stB[2] = {(__half*)dsmc + 2 * SZAH,
                      (__half*)dsmc + 2 * SZAH + SZBH};

    float acc[4][4][4];
    #pragma unroll
    for (int i = 0; i < 4; i++)
        #pragma unroll
        for (int j = 0; j < 4; j++)
            #pragma unroll
            for (int r = 0; r < 4; r++) acc[i][j][r] = 0.f;

    const float*  keyb  = key + (size_t)b * T * E + (size_t)t0 * E;
    const __half* featb = g_feath + ((size_t)b * T + t0) * F;

    int rowA[4], cgA[4];
    #pragma unroll
    for (int i = 0; i < 4; i++) {
        int li = tid + i * 256;
        rowA[i] = li >> 3;
        cgA[i]  = (li & 7) * 4;
    }

    int aRowOff = lr + (lg & 1) * 8;
    int aKOff   = (lg >> 1) * 8;
    int bColOff = (lg >> 1) * 8 + lr;
    int bKOff   = (lg & 1) * 8;

    // ---- prologue: chunk 0 into buffers 0; prefetch chunk-1 regs ----
    uint2 hPre[4];
    #pragma unroll
    for (int i = 0; i < 4; i++) {
        float4 a4 = *(const float4*)(keyb + (size_t)rowA[i] * E + cgA[i]);
        hPre[i].x = pack_h2(a4.x, a4.y);
        hPre[i].y = pack_h2(a4.z, a4.w);
    }
    #pragma unroll
    for (int i = 0; i < 2; i++) {
        int u = tid + i * 256;
        int col = u >> 2, kg8 = (u & 3) * 8;
        cp16(stB[0] + col * SBH + kg8, g_wbh + col * KC + kg8);
    }
    asm volatile("cp.async.commit_group;");
    #pragma unroll
    for (int i = 0; i < 4; i++)
        *(uint2*)(stA[0] + rowA[i] * SAH + cgA[i]) = hPre[i];
    // prefetch chunk-1 regs
    {
        int e0 = KC;
        #pragma unroll
        for (int i = 0; i < 4; i++) {
            float4 a4 = *(const float4*)(keyb + (size_t)rowA[i] * E + e0 + cgA[i]);
            hPre[i].x = pack_h2(a4.x, a4.y);
            hPre[i].y = pack_h2(a4.z, a4.w);
        }
    }
    asm volatile("cp.async.wait_group 0;");
    __syncthreads();

    for (int c = 0; c < NCHUNK; c++) {
        int buf = c & 1;
        __half* sA = stA[buf];
        __half* sB = stB[buf];
        bool has_next = (c + 1 < NCHUNK);

        // launch B(c+1) cp.async early
        if (has_next) {
            const __half* wsrc = g_wbh + (size_t)(c + 1) * (KC * A);
            __half* sBn = stB[buf ^ 1];
            #pragma unroll
            for (int i = 0; i < 2; i++) {
                int u = tid + i * 256;
                int col = u >> 2, kg8 = (u & 3) * 8;
                cp16(sBn + col * SBH + kg8, wsrc + col * KC + kg8);
            }
            asm volatile("cp.async.commit_group;");
        }

        // ---- MMA over buffer c ----
        #pragma unroll
        for (int ks = 0; ks < 2; ks++) {
            int k0 = ks * 16;
            uint32_t af[4][4];
            #pragma unroll
            for (int mf = 0; mf < 4; mf++) {
                const __half* pa = sA + (warp_m * 64 + mf * 16 + aRowOff) * SAH
                                 + k0 + aKOff;
                ldsm_x4(af[mf][0], af[mf][1], af[mf][2], af[mf][3], pa);
            }
            uint32_t bf[4][2];
            const __half* pb0 = sB + (warp_n * 32 + bColOff) * SBH + k0 + bKOff;
            ldsm_x4(bf[0][0], bf[0][1], bf[1][0], bf[1][1], pb0);
            ldsm_x4(bf[2][0], bf[2][1], bf[3][0], bf[3][1], pb0 + 16 * SBH);
            #pragma unroll
            for (int mf = 0; mf < 4; mf++)
                #pragma unroll
                for (int nf = 0; nf < 4; nf++)
                    mma_f16(acc[mf][nf][0], acc[mf][nf][1],
                            acc[mf][nf][2], acc[mf][nf][3],
                            af[mf][0], af[mf][1], af[mf][2], af[mf][3],
                            bf[nf][0], bf[nf][1]);
        }

        if (has_next) {
            // STS chunk c+1 into other A buffer (safe: its readers finished at
            // the barrier ending chunk c-1)
            #pragma unroll
            for (int i = 0; i < 4; i++)
                *(uint2*)(stA[buf ^ 1] + rowA[i] * SAH + cgA[i]) = hPre[i];
            // prefetch chunk c+2 regs (latency covered by next chunk's MMA)
            if (c + 2 < NCHUNK) {
                if (c + 2 < 16) {
                    int e0 = (c + 2) * KC;
                    #pragma unroll
                    for (int i = 0; i < 4; i++) {
                        float4 a4 = *(const float4*)(keyb + (size_t)rowA[i] * E + e0 + cgA[i]);
                        hPre[i].x = pack_h2(a4.x, a4.y);
                        hPre[i].y = pack_h2(a4.z, a4.w);
                    }
                } else {
                    #pragma unroll
                    for (int i = 0; i < 4; i++)
                        hPre[i] = *(const uint2*)(featb + (size_t)rowA[i] * F + cgA[i]);
                }
            }
            asm volatile("cp.async.wait_group 0;");
            __syncthreads();
        }
    }

    // ---- epilogue: e[t] = sum_a v[a] * tanh(q[a] + S[t,a]) ----
    float part[4][2];
    #pragma unroll
    for (int mf = 0; mf < 4; mf++) { part[mf][0] = 0.f; part[mf][1] = 0.f; }

    #pragma unroll
    for (int nf = 0; nf < 4; nf++) {
        int c0 = warp_n * 32 + nf * 8 + 2 * (lane & 3);
        float qv0 = g_qpart[(b * 4 + 0) * A + c0] + g_qpart[(b * 4 + 1) * A + c0]
                  + g_qpart[(b * 4 + 2) * A + c0] + g_qpart[(b * 4 + 3) * A + c0];
        float qv1 = g_qpart[(b * 4 + 0) * A + c0 + 1] + g_qpart[(b * 4 + 1) * A + c0 + 1]
                  + g_qpart[(b * 4 + 2) * A + c0 + 1] + g_qpart[(b * 4 + 3) * A + c0 + 1];
        float vv0 = v[c0],               vv1 = v[c0 + 1];
        #pragma unroll
        for (int mf = 0; mf < 4; mf++) {
            part[mf][0] += vv0 * tanhf(qv0 + acc[mf][nf][0])
                         + vv1 * tanhf(qv1 + acc[mf][nf][1]);
            part[mf][1] += vv0 * tanhf(qv0 + acc[mf][nf][2])
                         + vv1 * tanhf(qv1 + acc[mf][nf][3]);
        }
    }

    __syncthreads();
    float* red = (float*)dsmc;               // reuse: [128][5]
    #pragma unroll
    for (int mf = 0; mf < 4; mf++) {
        #pragma unroll
        for (int r = 0; r < 2; r++) {
            float p = part[mf][r];
            p += __shfl_xor_sync(0xFFFFFFFFu, p, 1);
            p += __shfl_xor_sync(0xFFFFFFFFu, p, 2);
            if ((lane & 3) == 0) {
                int row = warp_m * 64 + mf * 16 + (lane >> 2) + r * 8;
                red[row * 5 + warp_n] = p;
            }
        }
    }
    __syncthreads();

    if (tid < TM) {
        float s = red[tid * 5 + 0] + red[tid * 5 + 1]
                + red[tid * 5 + 2] + red[tid * 5 + 3];
        int t = t0 + tid;
        int mode = (!g_mflags[0]) ? 1 : ((!g_mflags[1]) ? 2 : 0);
        g_e[b * T + t] = read_mask(mask, b * T + t, mode) ? -INFINITY : s;
    }
}

// ---------------------------------------------------------------------------
// ctx: inline softmax + context partial + last-block final reduce (ticketed)
// ---------------------------------------------------------------------------
__global__ void __launch_bounds__(256)
ctx_kernel(const float* __restrict__ key,
           float* __restrict__ out) {
    int b = blockIdx.y;
    int c = blockIdx.x;             // 0..15, 64 t each
    int tid = threadIdx.x;          // 256
    int e4 = tid & 127, h = tid >> 7;

    __shared__ float sred[256];
    __shared__ float ws[64];
    __shared__ int s_last;

    float vals[4];
    float m = -INFINITY;
    #pragma unroll
    for (int i = 0; i < 4; i++) {
        vals[i] = g_e[b * T + tid + i * 256];
        m = fmaxf(m, vals[i]);
    }
    sred[tid] = m; __syncthreads();
    for (int s = 128; s > 0; s >>= 1) {
        if (tid < s) sred[tid] = fmaxf(sred[tid], sred[tid + s]);
        __syncthreads();
    }
    m = sred[0]; __syncthreads();

    float sum = 0.f;
    #pragma unroll
    for (int i = 0; i < 4; i++)
        sum += expf(vals[i] - m);
    sred[tid] = sum; __syncthreads();
    for (int s = 128; s > 0; s >>= 1) {
        if (tid < s) sred[tid] += sred[tid + s];
        __syncthreads();
    }
    float inv = 1.f / sred[0];
    __syncthreads();

    if (tid < 64) {
        float w = expf(g_e[b * T + c * 64 + tid] - m) * inv;
        ws[tid] = w;
        out[B * E + (size_t)b * T + c * 64 + tid] = w;
    }
    __syncthreads();

    const float* w = ws + h * 32;
    const float4* kp = (const float4*)(key + (size_t)b * T * E)
                     + (size_t)(c * 64 + h * 32) * (E / 4) + e4;
    float4 acc = make_float4(0.f, 0.f, 0.f, 0.f);
    #pragma unroll 8
    for (int t = 0; t < 32; t++) {
        float4 k4 = kp[(size_t)t * (E / 4)];
        float wt = w[t];
        acc.x += wt * k4.x; acc.y += wt * k4.y;
        acc.z += wt * k4.z; acc.w += wt * k4.w;
    }
    __shared__ float4 sred4[256];
    sred4[tid] = acc;
    __syncthreads();
    if (h == 0) {
        float4 o = sred4[tid];
        float4 p = sred4[tid + 128];
        o.x += p.x; o.y += p.y; o.z += p.z; o.w += p.w;
        g_ctxpart4[(b * 16 + c) * (E / 4) + e4] = o;
    }
    __threadfence();
    __syncthreads();

    if (tid == 0)
        s_last = (atomicAdd(&g_cnt[b], 1) == 15);
    __syncthreads();
    if (s_last) {
        const float* parts = (const float*)g_ctxpart4;
        #pragma unroll 1
        for (int e = tid; e < E; e += 256) {
            float s = 0.f;
            #pragma unroll
            for (int k = 0; k < 16; k++)
                s += parts[(b * 16 + k) * E + e];
            out[(size_t)b * E + e] = s;
        }
    }
}

// ---------------------------------------------------------------------------
extern "C" void kernel_launch(void* const* d_in, const int* in_sizes, int n_in,
                              void* d_out, int out_size) {
    const float* query  = (const float*)d_in[0];
    const float* key    = (const float*)d_in[1];
    const float* cat    = (const float*)d_in[2];
    const void*  mask   = (const void*)d_in[3];
    const float* Wq     = (const float*)d_in[4];
    const float* Wk     = (const float*)d_in[5];
    const float* conv_w = (const float*)d_in[6];
    const float* gamma  = (const float*)d_in[7];
    const float* beta   = (const float*)d_in[8];
    const float* mean   = (const float*)d_in[9];
    const float* var    = (const float*)d_in[10];
    const float* Wloc   = (const float*)d_in[11];
    const float* v      = (const float*)d_in[12];
    float* out = (float*)d_out;

    cudaFuncSetAttribute(energy_kernel,
                         cudaFuncAttributeMaxDynamicSharedMemorySize, SMEM_BYTES);

    prep_kernel<<<NB_PREP, 256>>>(query, Wq, cat, conv_w, gamma, beta, mean, var,
                                  Wk, Wloc, (const unsigned int*)mask);
    energy_kernel<<<dim3(T / TM, B), 256, SMEM_BYTES>>>(key, mask, v);
    ctx_kernel<<<dim3(16, B), 256>>>(key, out);
}

// round 17
// speedup vs baseline: 1.0807x; 1.0807x over previous
#include <cuda_runtime.h>
#include <cuda_fp16.h>
#include <math.h>
#include <stdint.h>

#define B 64
#define T 1024
#define E 512
#define R 1024
#define A 128
#define F 32
#define KS 31
#define PADC 15

#define TM 128          // t-tile of energy GEMM
#define KC 32           // k-chunk
#define NCHUNK 17       // 16 key chunks + 1 feat/Wloc chunk
#define SAH 40          // A smem row stride (halves) -> conflict-free frags
#define SBH 40          // B smem col stride (halves)
#define SZAH (TM * SAH) // 5120 halves = 10240 B
#define SZBH (A * SBH)  // 5120 halves = 10240 B
#define SMEM_BYTES ((SZAH + 2 * SZBH) * 2)   // 30720 B

// prep grid layout
#define NB_LOC  1024    // 16 per batch (64 t each; thread = one f x 8 t)
#define NB_QP   256     // 4 per batch (256 r each, 2 thread-groups of 128 r)
#define NB_WB   68
#define NB_MS   16
#define NB_PREP (NB_LOC + NB_QP + NB_WB + NB_MS)

// scratch (allocation-free rule: __device__ globals)
__device__ float  g_qpart[B * 4 * A];
__device__ __half g_feath[(size_t)B * T * F];        // [B][T][F] half
__device__ float  g_e[B * T];
__device__ float4 g_ctxpart4[B * 16 * E / 4];
__device__ __half g_wbh[(E + F) * A];                // per-chunk [col a][k] half
__device__ int    g_mflags[2];
__device__ int    g_cnt[B];

// ---------------------------------------------------------------------------
__device__ __forceinline__ void cp16(void* dst_smem, const void* src) {
    uint32_t d = (uint32_t)__cvta_generic_to_shared(dst_smem);
    asm volatile("cp.async.ca.shared.global [%0], [%1], 16;" :: "r"(d), "l"(src));
}
__device__ __forceinline__ void mma_f16(float& c0, float& c1, float& c2, float& c3,
                                        uint32_t a0, uint32_t a1, uint32_t a2, uint32_t a3,
                                        uint32_t b0, uint32_t b1) {
    asm volatile(
        "mma.sync.aligned.m16n8k16.row.col.f32.f16.f16.f32 "
        "{%0,%1,%2,%3}, {%4,%5,%6,%7}, {%8,%9}, {%0,%1,%2,%3};"
        : "+f"(c0), "+f"(c1), "+f"(c2), "+f"(c3)
        : "r"(a0), "r"(a1), "r"(a2), "r"(a3), "r"(b0), "r"(b1));
}
__device__ __forceinline__ void ldsm_x4(uint32_t& r0, uint32_t& r1,
                                        uint32_t& r2, uint32_t& r3,
                                        const __half* p) {
    uint32_t a = (uint32_t)__cvta_generic_to_shared(p);
    asm volatile("ldmatrix.sync.aligned.m8n8.x4.shared.b16 {%0,%1,%2,%3}, [%4];"
                 : "=r"(r0), "=r"(r1), "=r"(r2), "=r"(r3) : "r"(a));
}
__device__ __forceinline__ bool read_mask(const void* m, int idx, int mode) {
    if (mode == 1) return ((const int*)m)[idx] != 0;
    if (mode == 2) return ((const float*)m)[idx] != 0.f;
    return ((const unsigned char*)m)[idx] != 0;
}
__device__ __forceinline__ uint32_t pack_h2(float a, float b) {
    __half2 h = __floats2half2_rn(a, b);
    return *(uint32_t*)&h;
}

// ---------------------------------------------------------------------------
// PREP: fused loc-conv / qproj-partials / wbT(half) / mask-sniff
// ---------------------------------------------------------------------------
__global__ void __launch_bounds__(256)
prep_kernel(const float* __restrict__ query,
            const float* __restrict__ Wq,
            const float* __restrict__ cat,
            const float* __restrict__ conv_w,
            const float* __restrict__ gamma,
            const float* __restrict__ beta,
            const float* __restrict__ mean,
            const float* __restrict__ var,
            const float* __restrict__ Wk,
            const float* __restrict__ Wloc,
            const unsigned int* __restrict__ maskw) {
    int blk = blockIdx.x;
    int tid = threadIdx.x;

    if (blk < NB_LOC) {
        // ---- loc: conv1d->relu->BN; thread = (f, 8 t's), reg sliding window ----
        int b  = blk >> 4;
        int t0 = (blk & 15) * 64;
        int f  = tid & 31;
        int tg = tid >> 5;                  // 0..7 -> t = t0 + tg*8 + j

        __shared__ float xs[2][112];        // 64 + 30 halo
        __shared__ float cwS[32 * 63];      // [f][62] stride 63 (conflict-free)
        __shared__ float bnS[F], bnB[F];

        for (int idx = tid; idx < 2 * 94; idx += 256) {
            int ch = idx / 94, p = idx % 94;
            int tt = t0 - PADC + p;
            xs[ch][p] = (tt >= 0 && tt < T)
                      ? cat[(size_t)b * 2 * T + (size_t)ch * T + tt] : 0.f;
        }
        for (int idx = tid; idx < 32 * 62; idx += 256)
            cwS[(idx / 62) * 63 + (idx % 62)] = conv_w[idx];
        if (tid < F) {
            float s = rsqrtf(var[tid] + 1e-5f) * gamma[tid];
            bnS[tid] = s;
            bnB[tid] = beta[tid] - mean[tid] * s;
        }
        __syncthreads();

        float acc[8];
        #pragma unroll
        for (int j = 0; j < 8; j++) acc[j] = 0.f;

        const float* wrow = cwS + f * 63;
        #pragma unroll
        for (int ch = 0; ch < 2; ch++) {
            float xw[8];
            #pragma unroll
            for (int j = 0; j < 8; j++) xw[j] = xs[ch][tg * 8 + j];
            #pragma unroll
            for (int k = 0; k < KS; k++) {
                float wv = wrow[ch * KS + k];
                #pragma unroll
                for (int j = 0; j < 8; j++) acc[j] += xw[j] * wv;
                if (k < KS - 1) {
                    #pragma unroll
                    for (int j = 0; j < 7; j++) xw[j] = xw[j + 1];
                    xw[7] = xs[ch][tg * 8 + k + 8];
                }
            }
        }

        float s = bnS[f], bb = bnB[f];
        size_t base = ((size_t)b * T + t0 + tg * 8) * F + f;
        #pragma unroll
        for (int j = 0; j < 8; j++)
            g_feath[base + (size_t)j * F] = __float2half_rn(fmaxf(acc[j], 0.f) * s + bb);
    } else if (blk < NB_LOC + NB_QP) {
        // ------------ qproj partials: 4 blocks/b x 2 groups of 128 r ------------
        int idx = blk - NB_LOC;
        int b = idx >> 2, rr = idx & 3;
        int g = tid >> 7, a = tid & 127;
        __shared__ float sred[2][128];
        const float* qb = query + (size_t)b * R + rr * 256 + g * 128;
        const float* wp = Wq + (size_t)(rr * 256 + g * 128) * A + a;
        float acc = 0.f;
        #pragma unroll 16
        for (int r = 0; r < 128; r++)
            acc += qb[r] * wp[(size_t)r * A];
        sred[g][a] = acc;
        __syncthreads();
        if (g == 0)
            g_qpart[(b * 4 + rr) * A + a] = sred[0][a] + sred[1][a];
    } else if (blk < NB_LOC + NB_QP + NB_WB) {
        // ------ wbT: Wk ++ Wloc -> half, transposed per chunk [col a][k] ------
        int base = (blk - NB_LOC - NB_QP) * 1024;
        #pragma unroll
        for (int i = 0; i < 4; i++) {
            int idx = base + i * 256 + tid;
            int kg = idx >> 7, a = idx & 127;
            float x = (idx < E * A) ? Wk[idx] : Wloc[idx - E * A];
            int chunk = kg >> 5, kl = kg & 31;
            g_wbh[(size_t)chunk * (KC * A) + a * KC + kl] = __float2half_rn(x);
        }
    } else {
        // ---------------- mask sniff (16 blocks) + counter reset ----------------
        int ms = blk - NB_LOC - NB_QP - NB_WB;
        if (ms == 0 && tid < B) g_cnt[tid] = 0;
        __shared__ int s_not_int, s_not_flt;
        if (tid == 0) { s_not_int = 0; s_not_flt = 0; }
        __syncthreads();
        int not_int = 0, not_flt = 0;
        #pragma unroll
        for (int i = 0; i < 4; i++) {
            unsigned int x = maskw[ms * 1024 + i * 256 + tid];
            if (x > 1u) not_int = 1;
            if (x != 0u && x != 0x3F800000u) not_flt = 1;
        }
        if (not_int) atomicOr(&s_not_int, 1);
        if (not_flt) atomicOr(&s_not_flt, 1);
        __syncthreads();
        if (tid == 0) {
            if (s_not_int) atomicOr(&g_mflags[0], 1);
            if (s_not_flt) atomicOr(&g_mflags[1], 1);
        }
    }
}

// ---------------------------------------------------------------------------
// energy: fp16 MMA (m16n8k16) 128x128x(512+32), ldmatrix fragment loads
// (exact R14 structure)
// ---------------------------------------------------------------------------
__global__ void __launch_bounds__(256, 2)
energy_kernel(const float* __restrict__ key,
              const void* __restrict__ mask,
              const float* __restrict__ v) {
    int b  = blockIdx.y;
    int t0 = blockIdx.x * TM;
    int tid = threadIdx.x;
    int lane = tid & 31;
    int wid  = tid >> 5;
    int warp_m = wid >> 2;
    int warp_n = wid & 3;
    int lg = lane >> 3;
    int lr = lane & 7;

    extern __shared__ char dsmc[];
    __half* sAh = (__half*)dsmc;                         // [128][SAH]
    __half* stB[2] = {(__half*)dsmc + SZAH,
                      (__half*)dsmc + SZAH + SZBH};

    float acc[4][4][4];
    #pragma unroll
    for (int i = 0; i < 4; i++)
        #pragma unroll
        for (int j = 0; j < 4; j++)
            #pragma unroll
            for (int r = 0; r < 4; r++) acc[i][j][r] = 0.f;

    const float*  keyb  = key + (size_t)b * T * E + (size_t)t0 * E;
    const __half* featb = g_feath + ((size_t)b * T + t0) * F;

    int rowA[4], cgA[4];
    #pragma unroll
    for (int i = 0; i < 4; i++) {
        int li = tid + i * 256;
        rowA[i] = li >> 3;
        cgA[i]  = (li & 7) * 4;
    }

    int aRowOff = lr + (lg & 1) * 8;
    int aKOff   = (lg >> 1) * 8;
    int bColOff = (lg >> 1) * 8 + lr;
    int bKOff   = (lg & 1) * 8;

    // ---- prologue: chunk 0 ----
    uint2 hPre[4];
    #pragma unroll
    for (int i = 0; i < 4; i++) {
        float4 a4 = *(const float4*)(keyb + (size_t)rowA[i] * E + cgA[i]);
        hPre[i].x = pack_h2(a4.x, a4.y);
        hPre[i].y = pack_h2(a4.z, a4.w);
    }
    #pragma unroll
    for (int i = 0; i < 2; i++) {
        int u = tid + i * 256;
        int col = u >> 2, kg8 = (u & 3) * 8;
        cp16(stB[0] + col * SBH + kg8, g_wbh + col * KC + kg8);
    }
    asm volatile("cp.async.commit_group;");
    #pragma unroll
    for (int i = 0; i < 4; i++)
        *(uint2*)(sAh + rowA[i] * SAH + cgA[i]) = hPre[i];
    asm volatile("cp.async.wait_group 0;");
    __syncthreads();

    for (int c = 0; c < NCHUNK; c++) {
        __half* sB = stB[c & 1];
        bool has_next = (c + 1 < NCHUNK);
        if (has_next) {
            if (c + 1 < 16) {
                int e0 = (c + 1) * KC;
                #pragma unroll
                for (int i = 0; i < 4; i++) {
                    float4 a4 = *(const float4*)(keyb + (size_t)rowA[i] * E + e0 + cgA[i]);
                    hPre[i].x = pack_h2(a4.x, a4.y);
                    hPre[i].y = pack_h2(a4.z, a4.w);
                }
            } else {
                #pragma unroll
                for (int i = 0; i < 4; i++)
                    hPre[i] = *(const uint2*)(featb + (size_t)rowA[i] * F + cgA[i]);
            }
            const __half* wsrc = g_wbh + (size_t)(c + 1) * (KC * A);
            __half* sBn = stB[(c + 1) & 1];
            #pragma unroll
            for (int i = 0; i < 2; i++) {
                int u = tid + i * 256;
                int col = u >> 2, kg8 = (u & 3) * 8;
                cp16(sBn + col * SBH + kg8, wsrc + col * KC + kg8);
            }
            asm volatile("cp.async.commit_group;");
        }

        // ---- 2 k-steps of m16n8k16, ldmatrix fragment loads ----
        #pragma unroll
        for (int ks = 0; ks < 2; ks++) {
            int k0 = ks * 16;
            uint32_t af[4][4];
            #pragma unroll
            for (int mf = 0; mf < 4; mf++) {
                const __half* pa = sAh + (warp_m * 64 + mf * 16 + aRowOff) * SAH
                                 + k0 + aKOff;
                ldsm_x4(af[mf][0], af[mf][1], af[mf][2], af[mf][3], pa);
            }
            uint32_t bf[4][2];
            const __half* pb0 = sB + (warp_n * 32 + bColOff) * SBH + k0 + bKOff;
            ldsm_x4(bf[0][0], bf[0][1], bf[1][0], bf[1][1], pb0);
            ldsm_x4(bf[2][0], bf[2][1], bf[3][0], bf[3][1], pb0 + 16 * SBH);
            #pragma unroll
            for (int mf = 0; mf < 4; mf++)
                #pragma unroll
                for (int nf = 0; nf < 4; nf++)
                    mma_f16(acc[mf][nf][0], acc[mf][nf][1],
                            acc[mf][nf][2], acc[mf][nf][3],
                            af[mf][0], af[mf][1], af[mf][2], af[mf][3],
                            bf[nf][0], bf[nf][1]);
        }
        __syncthreads();

        if (has_next) {
            #pragma unroll
            for (int i = 0; i < 4; i++)
                *(uint2*)(sAh + rowA[i] * SAH + cgA[i]) = hPre[i];
            asm volatile("cp.async.wait_group 0;");
            __syncthreads();
        }
    }

    // ---- epilogue: e[t] = sum_a v[a] * tanh(q[a] + S[t,a]) ----
    float part[4][2];
    #pragma unroll
    for (int mf = 0; mf < 4; mf++) { part[mf][0] = 0.f; part[mf][1] = 0.f; }

    #pragma unroll
    for (int nf = 0; nf < 4; nf++) {
        int c0 = warp_n * 32 + nf * 8 + 2 * (lane & 3);
        float qv0 = g_qpart[(b * 4 + 0) * A + c0] + g_qpart[(b * 4 + 1) * A + c0]
                  + g_qpart[(b * 4 + 2) * A + c0] + g_qpart[(b * 4 + 3) * A + c0];
        float qv1 = g_qpart[(b * 4 + 0) * A + c0 + 1] + g_qpart[(b * 4 + 1) * A + c0 + 1]
                  + g_qpart[(b * 4 + 2) * A + c0 + 1] + g_qpart[(b * 4 + 3) * A + c0 + 1];
        float vv0 = v[c0],               vv1 = v[c0 + 1];
        #pragma unroll
        for (int mf = 0; mf < 4; mf++) {
            part[mf][0] += vv0 * tanhf(qv0 + acc[mf][nf][0])
                         + vv1 * tanhf(qv1 + acc[mf][nf][1]);
            part[mf][1] += vv0 * tanhf(qv0 + acc[mf][nf][2])
                         + vv1 * tanhf(qv1 + acc[mf][nf][3]);
        }
    }

    __syncthreads();
    float* red = (float*)dsmc;               // reuse: [128][5]
    #pragma unroll
    for (int mf = 0; mf < 4; mf++) {
        #pragma unroll
        for (int r = 0; r < 2; r++) {
            float p = part[mf][r];
            p += __shfl_xor_sync(0xFFFFFFFFu, p, 1);
            p += __shfl_xor_sync(0xFFFFFFFFu, p, 2);
            if ((lane & 3) == 0) {
                int row = warp_m * 64 + mf * 16 + (lane >> 2) + r * 8;
                red[row * 5 + warp_n] = p;
            }
        }
    }
    __syncthreads();

    if (tid < TM) {
        float s = red[tid * 5 + 0] + red[tid * 5 + 1]
                + red[tid * 5 + 2] + red[tid * 5 + 3];
        int t = t0 + tid;
        int mode = (!g_mflags[0]) ? 1 : ((!g_mflags[1]) ? 2 : 0);
        g_e[b * T + t] = read_mask(mask, b * T + t, mode) ? -INFINITY : s;
    }
}

// ---------------------------------------------------------------------------
// ctx: inline softmax + context partial + last-block final reduce (ticketed)
// ---------------------------------------------------------------------------
__global__ void __launch_bounds__(256)
ctx_kernel(const float* __restrict__ key,
           float* __restrict__ out) {
    int b = blockIdx.y;
    int c = blockIdx.x;             // 0..15, 64 t each
    int tid = threadIdx.x;          // 256
    int e4 = tid & 127, h = tid >> 7;

    __shared__ float sred[256];
    __shared__ float ws[64];
    __shared__ int s_last;

    float vals[4];
    float m = -INFINITY;
    #pragma unroll
    for (int i = 0; i < 4; i++) {
        vals[i] = g_e[b * T + tid + i * 256];
        m = fmaxf(m, vals[i]);
    }
    sred[tid] = m; __syncthreads();
    for (int s = 128; s > 0; s >>= 1) {
        if (tid < s) sred[tid] = fmaxf(sred[tid], sred[tid + s]);
        __syncthreads();
    }
    m = sred[0]; __syncthreads();

    float sum = 0.f;
    #pragma unroll
    for (int i = 0; i < 4; i++)
        sum += expf(vals[i] - m);
    sred[tid] = sum; __syncthreads();
    for (int s = 128; s > 0; s >>= 1) {
        if (tid < s) sred[tid] += sred[tid + s];
        __syncthreads();
    }
    float inv = 1.f / sred[0];
    __syncthreads();

    if (tid < 64) {
        float w = expf(g_e[b * T + c * 64 + tid] - m) * inv;
        ws[tid] = w;
        out[B * E + (size_t)b * T + c * 64 + tid] = w;
    }
    __syncthreads();

    const float* w = ws + h * 32;
    const float4* kp = (const float4*)(key + (size_t)b * T * E)
                     + (size_t)(c * 64 + h * 32) * (E / 4) + e4;
    float4 acc = make_float4(0.f, 0.f, 0.f, 0.f);
    #pragma unroll 8
    for (int t = 0; t < 32; t++) {
        float4 k4 = kp[(size_t)t * (E / 4)];
        float wt = w[t];
        acc.x += wt * k4.x; acc.y += wt * k4.y;
        acc.z += wt * k4.z; acc.w += wt * k4.w;
    }
    __shared__ float4 sred4[256];
    sred4[tid] = acc;
    __syncthreads();
    if (h == 0) {
        float4 o = sred4[tid];
        float4 p = sred4[tid + 128];
        o.x += p.x; o.y += p.y; o.z += p.z; o.w += p.w;
        g_ctxpart4[(b * 16 + c) * (E / 4) + e4] = o;
    }
    __threadfence();
    __syncthreads();

    if (tid == 0)
        s_last = (atomicAdd(&g_cnt[b], 1) == 15);
    __syncthreads();
    if (s_last) {
        const float* parts = (const float*)g_ctxpart4;
        #pragma unroll 1
        for (int e = tid; e < E; e += 256) {
            float s = 0.f;
            #pragma unroll
            for (int k = 0; k < 16; k++)
                s += parts[(b * 16 + k) * E + e];
            out[(size_t)b * E + e] = s;
        }
    }
}

// ---------------------------------------------------------------------------
extern "C" void kernel_launch(void* const* d_in, const int* in_sizes, int n_in,
                              void* d_out, int out_size) {
    const float* query  = (const float*)d_in[0];
    const float* key    = (const float*)d_in[1];
    const float* cat    = (const float*)d_in[2];
    const void*  mask   = (const void*)d_in[3];
    const float* Wq     = (const float*)d_in[4];
    const float* Wk     = (const float*)d_in[5];
    const float* conv_w = (const float*)d_in[6];
    const float* gamma  = (const float*)d_in[7];
    const float* beta   = (const float*)d_in[8];
    const float* mean   = (const float*)d_in[9];
    const float* var    = (const float*)d_in[10];
    const float* Wloc   = (const float*)d_in[11];
    const float* v      = (const float*)d_in[12];
    float* out = (float*)d_out;

    cudaFuncSetAttribute(energy_kernel,
                         cudaFuncAttributeMaxDynamicSharedMemorySize, SMEM_BYTES);

    prep_kernel<<<NB_PREP, 256>>>(query, Wq, cat, conv_w, gamma, beta, mean, var,
                                  Wk, Wloc, (const unsigned int*)mask);
    energy_kernel<<<dim3(T / TM, B), 256, SMEM_BYTES>>>(key, mask, v);
    ctx_kernel<<<dim3(16, B), 256>>>(key, out);
}